// round 2
// baseline (speedup 1.0000x reference)
#include <cuda_runtime.h>
#include <cuda_bf16.h>
#include <math.h>

// Problem constants
#define BN      16384      // B*N sequences
#define HIDN    512        // LSTM hidden
#define G4      2048       // 4*HIDN
#define HLEN    15
#define DIM     1024
#define MT      64         // sequences (rows) per CTA
#define TPB     256
#define HS      516        // padded h row stride (floats)

// SMEM budgets (floats)
#define SMEM_A_FLOATS (MT*HS + 64*128 + G4*4 + G4 + MT*HLEN*4)   // 33024+8192+8192+2048+3840 = 55296
#define SMEM_A_BYTES  (SMEM_A_FLOATS*4)                           // 221184
#define SMEM_B_FLOATS (MT*HS + 64*128 + MT*2 + MT*16 + MT*16 + MT + MT) // 43520
#define SMEM_B_BYTES  (SMEM_B_FLOATS*4)                           // 174080

// Scratch (device globals: sanctioned alternative to cudaMalloc)
__device__ float g_c  [BN * HIDN];   // LSTM cell state
__device__ float g_hn [BN * HIDN];   // LSTM hidden state (also final h_n)
__device__ float g_alpha[32];        // per-batch fusion gate

__device__ __forceinline__ float sigmoid_f(float x) {
    return 1.0f / (1.0f + __expf(-x));
}
__device__ __forceinline__ float tanh_f(float x) {
    float a = fabsf(x);
    float e = __expf(-2.0f * a);
    float r = (1.0f - e) / (1.0f + e);
    return copysignf(r, x);
}

// ---------------------------------------------------------------------------
// Kernel A: persistent LSTM. grid = BN/MT = 256 CTAs, 256 threads.
// Each CTA owns 64 sequences; loops over 15 timesteps.
// Per step: gates[64][512][4] = h[64][512] @ W_hh^T (+ xg on the fly),
// then pointwise LSTM update. h round-trips via g_hn between steps.
// ---------------------------------------------------------------------------
__global__ __launch_bounds__(TPB, 1)
void lstm_kernel(const float* __restrict__ traj,    // (BN,15,4)
                 const float* __restrict__ W_ih,    // (2048,4)
                 const float* __restrict__ W_hh,    // (2048,512)
                 const float* __restrict__ b_ih,    // (2048)
                 const float* __restrict__ b_hh)    // (2048)
{
    extern __shared__ float sm[];
    float* h_s  = sm;                       // [64][516]
    float* Wt   = sm + MT*HS;               // [64][128]  Wt[kk*128 + c]
    float* wih  = Wt + 64*128;              // [2048][4]
    float* bias = wih + G4*4;               // [2048]
    float* trj  = bias + G4;                // [64][15][4]

    const int tid = threadIdx.x;
    const int tx  = tid & 15;               // 0..15 : k-group
    const int ty  = tid >> 4;               // 0..15 : m-group (4 rows each)
    const int m0  = blockIdx.x * MT;

    // one-time loads
    for (int i = tid; i < (MT*HLEN*4)/4; i += TPB)
        ((float4*)trj)[i] = ((const float4*)(traj + (size_t)m0 * (HLEN*4)))[i];
    for (int r = tid; r < G4; r += TPB) {
        ((float4*)wih)[r] = ((const float4*)W_ih)[r];
        bias[r] = b_ih[r] + b_hh[r];
    }
    __syncthreads();

    for (int t = 0; t < HLEN; ++t) {
        for (int ch = 0; ch < 16; ++ch) {
            const int kb0 = ch * 32;        // chunk covers k in [kb0, kb0+32)
            float acc[4][2][4];
            #pragma unroll
            for (int r = 0; r < 4; ++r)
                #pragma unroll
                for (int q = 0; q < 2; ++q)
                    #pragma unroll
                    for (int g = 0; g < 4; ++g) acc[r][q][g] = 0.0f;

            if (t > 0) {
                for (int kb = 0; kb < HIDN; kb += 64) {
                    __syncthreads();   // previous Wt readers done
                    // stage W_hh tile: 128 gate-cols x 64 K  (32B/lane coalesced)
                    #pragma unroll
                    for (int it = 0; it < 4; ++it) {
                        int s    = tid + it * TPB;      // 0..1023
                        int c    = s & 127;             // col: kl*4+gate
                        int sub  = s >> 7;              // 0..7
                        int gate = c & 3;
                        int kl   = c >> 2;
                        const float* src = W_hh + (size_t)(gate*HIDN + kb0 + kl)*HIDN + kb + sub*8;
                        float4 w0 = *(const float4*)src;
                        float4 w1 = *(const float4*)(src + 4);
                        float* dst = Wt + (sub*8)*128 + c;
                        dst[0*128]=w0.x; dst[1*128]=w0.y; dst[2*128]=w0.z; dst[3*128]=w0.w;
                        dst[4*128]=w1.x; dst[5*128]=w1.y; dst[6*128]=w1.z; dst[7*128]=w1.w;
                    }
                    __syncthreads();
                    #pragma unroll 4
                    for (int kk = 0; kk < 64; ++kk) {
                        float a[4];
                        #pragma unroll
                        for (int r = 0; r < 4; ++r)
                            a[r] = h_s[(ty*4 + r)*HS + kb + kk];
                        float4 b0 = *(float4*)(Wt + kk*128 + tx*8);
                        float4 b1 = *(float4*)(Wt + kk*128 + tx*8 + 4);
                        #pragma unroll
                        for (int r = 0; r < 4; ++r) {
                            acc[r][0][0] += a[r]*b0.x; acc[r][0][1] += a[r]*b0.y;
                            acc[r][0][2] += a[r]*b0.z; acc[r][0][3] += a[r]*b0.w;
                            acc[r][1][0] += a[r]*b1.x; acc[r][1][1] += a[r]*b1.y;
                            acc[r][1][2] += a[r]*b1.z; acc[r][1][3] += a[r]*b1.w;
                        }
                    }
                }
            }

            // epilogue: add xg (input contribution) + bias, LSTM pointwise update
            #pragma unroll
            for (int r = 0; r < 4; ++r) {
                int m  = ty*4 + r;
                int gm = m0 + m;
                float4 xv = *(float4*)(trj + m*(HLEN*4) + t*4);
                #pragma unroll
                for (int q = 0; q < 2; ++q) {
                    int k = kb0 + tx*2 + q;
                    float gv[4];
                    #pragma unroll
                    for (int gg = 0; gg < 4; ++gg) {
                        int row = gg*HIDN + k;
                        float4 w = ((float4*)wih)[row];
                        gv[gg] = acc[r][q][gg] + bias[row]
                               + xv.x*w.x + xv.y*w.y + xv.z*w.z + xv.w*w.w;
                    }
                    float ig = sigmoid_f(gv[0]);
                    float fg = sigmoid_f(gv[1]);
                    float gt = tanh_f(gv[2]);
                    float og = sigmoid_f(gv[3]);
                    size_t idx = (size_t)gm*HIDN + k;
                    float cprev = (t == 0) ? 0.0f : g_c[idx];
                    float cn = fg*cprev + ig*gt;
                    g_c[idx]  = cn;
                    g_hn[idx] = og * tanh_f(cn);
                }
            }
        } // chunks

        if (t < HLEN - 1) {
            __syncthreads();   // all g_hn writes of this step visible
            for (int i = tid; i < (MT*HIDN)/4; i += TPB) {
                int m  = i >> 7;          // 128 float4 per row
                int k4 = i & 127;
                float4 v = ((const float4*)(g_hn + (size_t)(m0 + m)*HIDN))[k4];
                *(float4*)(h_s + m*HS + k4*4) = v;
            }
            __syncthreads();
        }
    }
}

// ---------------------------------------------------------------------------
// Kernel G: per-batch fusion gate alpha (tiny MLP). 1 block, 32 threads.
// ---------------------------------------------------------------------------
__global__ void alpha_kernel(const float* __restrict__ ego_speed,
                             const float* __restrict__ gps_conf,
                             const float* __restrict__ W_g1,   // (16,2)
                             const float* __restrict__ b_g1,   // (16)
                             const float* __restrict__ W_g2,   // (1,16)
                             const float* __restrict__ b_g2)   // (1)
{
    int b = threadIdx.x;
    if (b < 32) {
        float s = ego_speed[b], c = gps_conf[b];
        float acc = b_g2[0];
        #pragma unroll
        for (int h = 0; h < 16; ++h) {
            float t = W_g1[2*h]*s + W_g1[2*h+1]*c + b_g1[h];
            t = fmaxf(t, 0.0f);
            acc += W_g2[h]*t;
        }
        g_alpha[b] = 1.0f / (1.0f + expf(-acc));
    }
}

// ---------------------------------------------------------------------------
// Kernel B: fused projection + alpha-blend + residual + LayerNorm.
// out = LN(tokens + alpha*(h_n@W_rel^T) + (1-alpha)*(habs@W_abs^T))
// grid = 256 CTAs x 64 rows; GEMM 64x1024x512 per CTA; two-pass LN in-block.
// ---------------------------------------------------------------------------
__global__ __launch_bounds__(TPB, 1)
void fuse_kernel(const float* __restrict__ tokens,  // (BN,1024)
                 const float* __restrict__ habs,    // (BN,2)
                 const float* __restrict__ W_rel,   // (1024,512)
                 const float* __restrict__ W_abs,   // (1024,2)
                 const float* __restrict__ gamma,
                 const float* __restrict__ beta,
                 float* __restrict__ out)           // (BN,1024)
{
    extern __shared__ float sm[];
    float* hs   = sm;                 // [64][516]
    float* Wt   = sm + MT*HS;         // [64][128]
    float* hb   = Wt + 64*128;        // [64][2]
    float* redS = hb + MT*2;          // [64][16]
    float* redQ = redS + MT*16;       // [64][16]
    float* mu_s = redQ + MT*16;       // [64]
    float* rs_s = mu_s + MT;          // [64]

    const int tid = threadIdx.x;
    const int tx  = tid & 15;
    const int ty  = tid >> 4;
    const int m0  = blockIdx.x * MT;

    for (int i = tid; i < (MT*HIDN)/4; i += TPB) {
        int m  = i >> 7;
        int k4 = i & 127;
        float4 v = ((const float4*)(g_hn + (size_t)(m0 + m)*HIDN))[k4];
        *(float4*)(hs + m*HS + k4*4) = v;
    }
    for (int i = tid; i < MT*2; i += TPB)
        hb[i] = habs[(size_t)m0*2 + i];
    __syncthreads();

    const float al  = g_alpha[m0 >> 9];   // all 64 rows share one batch index
    const float ali = 1.0f - al;

    float rs[4] = {0,0,0,0}, rq[4] = {0,0,0,0};

    for (int ch = 0; ch < 8; ++ch) {
        const int jb = ch * 128;
        float acc[4][8];
        #pragma unroll
        for (int r = 0; r < 4; ++r)
            #pragma unroll
            for (int cc = 0; cc < 8; ++cc) acc[r][cc] = 0.0f;

        for (int kb = 0; kb < HIDN; kb += 64) {
            __syncthreads();
            #pragma unroll
            for (int it = 0; it < 4; ++it) {
                int s   = tid + it * TPB;
                int c   = s & 127;
                int sub = s >> 7;
                const float* src = W_rel + (size_t)(jb + c)*HIDN + kb + sub*8;
                float4 w0 = *(const float4*)src;
                float4 w1 = *(const float4*)(src + 4);
                float* dst = Wt + (sub*8)*128 + c;
                dst[0*128]=w0.x; dst[1*128]=w0.y; dst[2*128]=w0.z; dst[3*128]=w0.w;
                dst[4*128]=w1.x; dst[5*128]=w1.y; dst[6*128]=w1.z; dst[7*128]=w1.w;
            }
            __syncthreads();
            #pragma unroll 4
            for (int kk = 0; kk < 64; ++kk) {
                float a[4];
                #pragma unroll
                for (int r = 0; r < 4; ++r)
                    a[r] = hs[(ty*4 + r)*HS + kb + kk];
                float4 b0 = *(float4*)(Wt + kk*128 + tx*8);
                float4 b1 = *(float4*)(Wt + kk*128 + tx*8 + 4);
                #pragma unroll
                for (int r = 0; r < 4; ++r) {
                    acc[r][0] += a[r]*b0.x; acc[r][1] += a[r]*b0.y;
                    acc[r][2] += a[r]*b0.z; acc[r][3] += a[r]*b0.w;
                    acc[r][4] += a[r]*b1.x; acc[r][5] += a[r]*b1.y;
                    acc[r][6] += a[r]*b1.z; acc[r][7] += a[r]*b1.w;
                }
            }
        }

        // chunk epilogue: blend + residual, store pre-LN x, track row sums
        #pragma unroll
        for (int r = 0; r < 4; ++r) {
            int m = ty*4 + r;
            int R = m0 + m;
            float h0 = hb[m*2], h1 = hb[m*2+1];
            const int j0 = jb + tx*8;
            float4 t0 = *(const float4*)(tokens + (size_t)R*DIM + j0);
            float4 t1 = *(const float4*)(tokens + (size_t)R*DIM + j0 + 4);
            float xv[8];
            float tk[8] = {t0.x,t0.y,t0.z,t0.w,t1.x,t1.y,t1.z,t1.w};
            #pragma unroll
            for (int cc = 0; cc < 8; ++cc) {
                int j = j0 + cc;
                float2 wa = ((const float2*)W_abs)[j];
                float ha = h0*wa.x + h1*wa.y;
                float x  = tk[cc] + al*acc[r][cc] + ali*ha;
                xv[cc] = x;
                rs[r] += x;
                rq[r] += x*x;
            }
            float4 o0 = make_float4(xv[0],xv[1],xv[2],xv[3]);
            float4 o1 = make_float4(xv[4],xv[5],xv[6],xv[7]);
            *(float4*)(out + (size_t)R*DIM + j0)     = o0;
            *(float4*)(out + (size_t)R*DIM + j0 + 4) = o1;
        }
    }

    // LayerNorm: reduce per row, then normalize in place
    __syncthreads();
    #pragma unroll
    for (int r = 0; r < 4; ++r) {
        redS[(ty*4 + r)*16 + tx] = rs[r];
        redQ[(ty*4 + r)*16 + tx] = rq[r];
    }
    __syncthreads();
    if (tid < MT) {
        float s = 0.0f, q = 0.0f;
        #pragma unroll
        for (int i = 0; i < 16; ++i) { s += redS[tid*16 + i]; q += redQ[tid*16 + i]; }
        float mu  = s * (1.0f/DIM);
        float var = q * (1.0f/DIM) - mu*mu;
        mu_s[tid] = mu;
        rs_s[tid] = rsqrtf(var + 1e-5f);
    }
    __syncthreads();
    for (int i = tid; i < (MT*DIM)/4; i += TPB) {
        int m  = i >> 8;           // 256 float4 per row
        int j4 = i & 255;
        float4 v = ((float4*)(out + (size_t)(m0 + m)*DIM))[j4];
        float4 g = ((const float4*)gamma)[j4];
        float4 b = ((const float4*)beta)[j4];
        float mu = mu_s[m], rr = rs_s[m];
        v.x = (v.x - mu)*rr*g.x + b.x;
        v.y = (v.y - mu)*rr*g.y + b.y;
        v.z = (v.z - mu)*rr*g.z + b.z;
        v.w = (v.w - mu)*rr*g.w + b.w;
        ((float4*)(out + (size_t)(m0 + m)*DIM))[j4] = v;
    }
}

// ---------------------------------------------------------------------------
extern "C" void kernel_launch(void* const* d_in, const int* in_sizes, int n_in,
                              void* d_out, int out_size)
{
    const float* tokens   = (const float*)d_in[0];
    const float* traj     = (const float*)d_in[1];
    const float* habs     = (const float*)d_in[2];
    const float* espeed   = (const float*)d_in[3];
    const float* gconf    = (const float*)d_in[4];
    const float* W_ih     = (const float*)d_in[5];
    const float* W_hh     = (const float*)d_in[6];
    const float* b_ih     = (const float*)d_in[7];
    const float* b_hh     = (const float*)d_in[8];
    const float* W_rel    = (const float*)d_in[9];
    const float* W_abs    = (const float*)d_in[10];
    const float* W_g1     = (const float*)d_in[11];
    const float* b_g1     = (const float*)d_in[12];
    const float* W_g2     = (const float*)d_in[13];
    const float* b_g2     = (const float*)d_in[14];
    const float* gamma    = (const float*)d_in[15];
    const float* beta     = (const float*)d_in[16];
    float* out = (float*)d_out;

    // opt-in to >48KB dynamic SMEM (idempotent; not a stream op)
    cudaFuncSetAttribute(lstm_kernel, cudaFuncAttributeMaxDynamicSharedMemorySize, SMEM_A_BYTES);
    cudaFuncSetAttribute(fuse_kernel, cudaFuncAttributeMaxDynamicSharedMemorySize, SMEM_B_BYTES);

    lstm_kernel<<<BN/MT, TPB, SMEM_A_BYTES>>>(traj, W_ih, W_hh, b_ih, b_hh);
    alpha_kernel<<<1, 32>>>(espeed, gconf, W_g1, b_g1, W_g2, b_g2);
    fuse_kernel<<<BN/MT, TPB, SMEM_B_BYTES>>>(tokens, habs, W_rel, W_abs, gamma, beta, out);
}

// round 3
// speedup vs baseline: 1.0016x; 1.0016x over previous
#include <cuda_runtime.h>
#include <cuda_bf16.h>
#include <math.h>

// Problem constants
#define BN      16384      // B*N sequences
#define HIDN    512        // LSTM hidden
#define G4      2048       // 4*HIDN
#define HLEN    15
#define DIM     1024
#define MT      64         // sequences (rows) per CTA
#define TPB     256
#define HS      516        // padded h row stride (floats)

// SMEM budgets (floats)
#define SMEM_A_FLOATS (MT*HS + 64*128 + G4*4 + G4 + MT*HLEN*4)   // 33024+8192+8192+2048+3840 = 55296
#define SMEM_A_BYTES  (SMEM_A_FLOATS*4)                           // 221184
#define SMEM_B_FLOATS (MT*HS + 64*128 + MT*2 + MT*16 + MT*16 + MT + MT) // 43520
#define SMEM_B_BYTES  (SMEM_B_FLOATS*4)                           // 174080

// Scratch (device globals: sanctioned alternative to cudaMalloc)
__device__ float g_c  [BN * HIDN];   // LSTM cell state
__device__ float g_hn [BN * HIDN];   // LSTM hidden state (also final h_n)
__device__ float g_alpha[32];        // per-batch fusion gate

__device__ __forceinline__ float sigmoid_f(float x) {
    return 1.0f / (1.0f + __expf(-x));
}
__device__ __forceinline__ float tanh_f(float x) {
    float a = fabsf(x);
    float e = __expf(-2.0f * a);
    float r = (1.0f - e) / (1.0f + e);
    return copysignf(r, x);
}

// ---------------------------------------------------------------------------
// Kernel A: persistent LSTM. grid = BN/MT = 256 CTAs, 256 threads.
// Each CTA owns 64 sequences; loops over 15 timesteps.
// Per step: gates[64][512][4] = h[64][512] @ W_hh^T (+ xg on the fly),
// then pointwise LSTM update. h round-trips via g_hn between steps.
// ---------------------------------------------------------------------------
__global__ __launch_bounds__(TPB, 1)
void lstm_kernel(const float* __restrict__ traj,    // (BN,15,4)
                 const float* __restrict__ W_ih,    // (2048,4)
                 const float* __restrict__ W_hh,    // (2048,512)
                 const float* __restrict__ b_ih,    // (2048)
                 const float* __restrict__ b_hh)    // (2048)
{
    extern __shared__ float sm[];
    float* h_s  = sm;                       // [64][516]
    float* Wt   = sm + MT*HS;               // [64][128]  Wt[kk*128 + c]
    float* wih  = Wt + 64*128;              // [2048][4]
    float* bias = wih + G4*4;               // [2048]
    float* trj  = bias + G4;                // [64][15][4]

    const int tid = threadIdx.x;
    const int tx  = tid & 15;               // 0..15 : k-group
    const int ty  = tid >> 4;               // 0..15 : m-group (4 rows each)
    const int m0  = blockIdx.x * MT;

    // one-time loads
    for (int i = tid; i < (MT*HLEN*4)/4; i += TPB)
        ((float4*)trj)[i] = ((const float4*)(traj + (size_t)m0 * (HLEN*4)))[i];
    for (int r = tid; r < G4; r += TPB) {
        ((float4*)wih)[r] = ((const float4*)W_ih)[r];
        bias[r] = b_ih[r] + b_hh[r];
    }
    __syncthreads();

    for (int t = 0; t < HLEN; ++t) {
        for (int ch = 0; ch < 16; ++ch) {
            const int kb0 = ch * 32;        // chunk covers k in [kb0, kb0+32)
            float acc[4][2][4];
            #pragma unroll
            for (int r = 0; r < 4; ++r)
                #pragma unroll
                for (int q = 0; q < 2; ++q)
                    #pragma unroll
                    for (int g = 0; g < 4; ++g) acc[r][q][g] = 0.0f;

            if (t > 0) {
                for (int kb = 0; kb < HIDN; kb += 64) {
                    __syncthreads();   // previous Wt readers done
                    // stage W_hh tile: 128 gate-cols x 64 K  (32B/lane coalesced)
                    #pragma unroll
                    for (int it = 0; it < 4; ++it) {
                        int s    = tid + it * TPB;      // 0..1023
                        int c    = s & 127;             // col: kl*4+gate
                        int sub  = s >> 7;              // 0..7
                        int gate = c & 3;
                        int kl   = c >> 2;
                        const float* src = W_hh + (size_t)(gate*HIDN + kb0 + kl)*HIDN + kb + sub*8;
                        float4 w0 = *(const float4*)src;
                        float4 w1 = *(const float4*)(src + 4);
                        float* dst = Wt + (sub*8)*128 + c;
                        dst[0*128]=w0.x; dst[1*128]=w0.y; dst[2*128]=w0.z; dst[3*128]=w0.w;
                        dst[4*128]=w1.x; dst[5*128]=w1.y; dst[6*128]=w1.z; dst[7*128]=w1.w;
                    }
                    __syncthreads();
                    #pragma unroll 4
                    for (int kk = 0; kk < 64; ++kk) {
                        float a[4];
                        #pragma unroll
                        for (int r = 0; r < 4; ++r)
                            a[r] = h_s[(ty*4 + r)*HS + kb + kk];
                        float4 b0 = *(float4*)(Wt + kk*128 + tx*8);
                        float4 b1 = *(float4*)(Wt + kk*128 + tx*8 + 4);
                        #pragma unroll
                        for (int r = 0; r < 4; ++r) {
                            acc[r][0][0] += a[r]*b0.x; acc[r][0][1] += a[r]*b0.y;
                            acc[r][0][2] += a[r]*b0.z; acc[r][0][3] += a[r]*b0.w;
                            acc[r][1][0] += a[r]*b1.x; acc[r][1][1] += a[r]*b1.y;
                            acc[r][1][2] += a[r]*b1.z; acc[r][1][3] += a[r]*b1.w;
                        }
                    }
                }
            }

            // epilogue: add xg (input contribution) + bias, LSTM pointwise update
            #pragma unroll
            for (int r = 0; r < 4; ++r) {
                int m  = ty*4 + r;
                int gm = m0 + m;
                float4 xv = *(float4*)(trj + m*(HLEN*4) + t*4);
                #pragma unroll
                for (int q = 0; q < 2; ++q) {
                    int k = kb0 + tx*2 + q;
                    float gv[4];
                    #pragma unroll
                    for (int gg = 0; gg < 4; ++gg) {
                        int row = gg*HIDN + k;
                        float4 w = ((float4*)wih)[row];
                        gv[gg] = acc[r][q][gg] + bias[row]
                               + xv.x*w.x + xv.y*w.y + xv.z*w.z + xv.w*w.w;
                    }
                    float ig = sigmoid_f(gv[0]);
                    float fg = sigmoid_f(gv[1]);
                    float gt = tanh_f(gv[2]);
                    float og = sigmoid_f(gv[3]);
                    size_t idx = (size_t)gm*HIDN + k;
                    float cprev = (t == 0) ? 0.0f : g_c[idx];
                    float cn = fg*cprev + ig*gt;
                    g_c[idx]  = cn;
                    g_hn[idx] = og * tanh_f(cn);
                }
            }
        } // chunks

        if (t < HLEN - 1) {
            __syncthreads();   // all g_hn writes of this step visible
            for (int i = tid; i < (MT*HIDN)/4; i += TPB) {
                int m  = i >> 7;          // 128 float4 per row
                int k4 = i & 127;
                float4 v = ((const float4*)(g_hn + (size_t)(m0 + m)*HIDN))[k4];
                *(float4*)(h_s + m*HS + k4*4) = v;
            }
            __syncthreads();
        }
    }
}

// ---------------------------------------------------------------------------
// Kernel G: per-batch fusion gate alpha (tiny MLP). 1 block, 32 threads.
// ---------------------------------------------------------------------------
__global__ void alpha_kernel(const float* __restrict__ ego_speed,
                             const float* __restrict__ gps_conf,
                             const float* __restrict__ W_g1,   // (16,2)
                             const float* __restrict__ b_g1,   // (16)
                             const float* __restrict__ W_g2,   // (1,16)
                             const float* __restrict__ b_g2)   // (1)
{
    int b = threadIdx.x;
    if (b < 32) {
        float s = ego_speed[b], c = gps_conf[b];
        float acc = b_g2[0];
        #pragma unroll
        for (int h = 0; h < 16; ++h) {
            float t = W_g1[2*h]*s + W_g1[2*h+1]*c + b_g1[h];
            t = fmaxf(t, 0.0f);
            acc += W_g2[h]*t;
        }
        g_alpha[b] = 1.0f / (1.0f + expf(-acc));
    }
}

// ---------------------------------------------------------------------------
// Kernel B: fused projection + alpha-blend + residual + LayerNorm.
// out = LN(tokens + alpha*(h_n@W_rel^T) + (1-alpha)*(habs@W_abs^T))
// grid = 256 CTAs x 64 rows; GEMM 64x1024x512 per CTA; two-pass LN in-block.
// ---------------------------------------------------------------------------
__global__ __launch_bounds__(TPB, 1)
void fuse_kernel(const float* __restrict__ tokens,  // (BN,1024)
                 const float* __restrict__ habs,    // (BN,2)
                 const float* __restrict__ W_rel,   // (1024,512)
                 const float* __restrict__ W_abs,   // (1024,2)
                 const float* __restrict__ gamma,
                 const float* __restrict__ beta,
                 float* __restrict__ out)           // (BN,1024)
{
    extern __shared__ float sm[];
    float* hs   = sm;                 // [64][516]
    float* Wt   = sm + MT*HS;         // [64][128]
    float* hb   = Wt + 64*128;        // [64][2]
    float* redS = hb + MT*2;          // [64][16]
    float* redQ = redS + MT*16;       // [64][16]
    float* mu_s = redQ + MT*16;       // [64]
    float* rs_s = mu_s + MT;          // [64]

    const int tid = threadIdx.x;
    const int tx  = tid & 15;
    const int ty  = tid >> 4;
    const int m0  = blockIdx.x * MT;

    for (int i = tid; i < (MT*HIDN)/4; i += TPB) {
        int m  = i >> 7;
        int k4 = i & 127;
        float4 v = ((const float4*)(g_hn + (size_t)(m0 + m)*HIDN))[k4];
        *(float4*)(hs + m*HS + k4*4) = v;
    }
    for (int i = tid; i < MT*2; i += TPB)
        hb[i] = habs[(size_t)m0*2 + i];
    __syncthreads();

    const float al  = g_alpha[m0 >> 9];   // all 64 rows share one batch index
    const float ali = 1.0f - al;

    float rs[4] = {0,0,0,0}, rq[4] = {0,0,0,0};

    for (int ch = 0; ch < 8; ++ch) {
        const int jb = ch * 128;
        float acc[4][8];
        #pragma unroll
        for (int r = 0; r < 4; ++r)
            #pragma unroll
            for (int cc = 0; cc < 8; ++cc) acc[r][cc] = 0.0f;

        for (int kb = 0; kb < HIDN; kb += 64) {
            __syncthreads();
            #pragma unroll
            for (int it = 0; it < 4; ++it) {
                int s   = tid + it * TPB;
                int c   = s & 127;
                int sub = s >> 7;
                const float* src = W_rel + (size_t)(jb + c)*HIDN + kb + sub*8;
                float4 w0 = *(const float4*)src;
                float4 w1 = *(const float4*)(src + 4);
                float* dst = Wt + (sub*8)*128 + c;
                dst[0*128]=w0.x; dst[1*128]=w0.y; dst[2*128]=w0.z; dst[3*128]=w0.w;
                dst[4*128]=w1.x; dst[5*128]=w1.y; dst[6*128]=w1.z; dst[7*128]=w1.w;
            }
            __syncthreads();
            #pragma unroll 4
            for (int kk = 0; kk < 64; ++kk) {
                float a[4];
                #pragma unroll
                for (int r = 0; r < 4; ++r)
                    a[r] = hs[(ty*4 + r)*HS + kb + kk];
                float4 b0 = *(float4*)(Wt + kk*128 + tx*8);
                float4 b1 = *(float4*)(Wt + kk*128 + tx*8 + 4);
                #pragma unroll
                for (int r = 0; r < 4; ++r) {
                    acc[r][0] += a[r]*b0.x; acc[r][1] += a[r]*b0.y;
                    acc[r][2] += a[r]*b0.z; acc[r][3] += a[r]*b0.w;
                    acc[r][4] += a[r]*b1.x; acc[r][5] += a[r]*b1.y;
                    acc[r][6] += a[r]*b1.z; acc[r][7] += a[r]*b1.w;
                }
            }
        }

        // chunk epilogue: blend + residual, store pre-LN x, track row sums
        #pragma unroll
        for (int r = 0; r < 4; ++r) {
            int m = ty*4 + r;
            int R = m0 + m;
            float h0 = hb[m*2], h1 = hb[m*2+1];
            const int j0 = jb + tx*8;
            float4 t0 = *(const float4*)(tokens + (size_t)R*DIM + j0);
            float4 t1 = *(const float4*)(tokens + (size_t)R*DIM + j0 + 4);
            float xv[8];
            float tk[8] = {t0.x,t0.y,t0.z,t0.w,t1.x,t1.y,t1.z,t1.w};
            #pragma unroll
            for (int cc = 0; cc < 8; ++cc) {
                int j = j0 + cc;
                float2 wa = ((const float2*)W_abs)[j];
                float ha = h0*wa.x + h1*wa.y;
                float x  = tk[cc] + al*acc[r][cc] + ali*ha;
                xv[cc] = x;
                rs[r] += x;
                rq[r] += x*x;
            }
            float4 o0 = make_float4(xv[0],xv[1],xv[2],xv[3]);
            float4 o1 = make_float4(xv[4],xv[5],xv[6],xv[7]);
            *(float4*)(out + (size_t)R*DIM + j0)     = o0;
            *(float4*)(out + (size_t)R*DIM + j0 + 4) = o1;
        }
    }

    // LayerNorm: reduce per row, then normalize in place
    __syncthreads();
    #pragma unroll
    for (int r = 0; r < 4; ++r) {
        redS[(ty*4 + r)*16 + tx] = rs[r];
        redQ[(ty*4 + r)*16 + tx] = rq[r];
    }
    __syncthreads();
    if (tid < MT) {
        float s = 0.0f, q = 0.0f;
        #pragma unroll
        for (int i = 0; i < 16; ++i) { s += redS[tid*16 + i]; q += redQ[tid*16 + i]; }
        float mu  = s * (1.0f/DIM);
        float var = q * (1.0f/DIM) - mu*mu;
        mu_s[tid] = mu;
        rs_s[tid] = rsqrtf(var + 1e-5f);
    }
    __syncthreads();
    for (int i = tid; i < (MT*DIM)/4; i += TPB) {
        int m  = i >> 8;           // 256 float4 per row
        int j4 = i & 255;
        float4 v = ((float4*)(out + (size_t)(m0 + m)*DIM))[j4];
        float4 g = ((const float4*)gamma)[j4];
        float4 b = ((const float4*)beta)[j4];
        float mu = mu_s[m], rr = rs_s[m];
        v.x = (v.x - mu)*rr*g.x + b.x;
        v.y = (v.y - mu)*rr*g.y + b.y;
        v.z = (v.z - mu)*rr*g.z + b.z;
        v.w = (v.w - mu)*rr*g.w + b.w;
        ((float4*)(out + (size_t)(m0 + m)*DIM))[j4] = v;
    }
}

// ---------------------------------------------------------------------------
extern "C" void kernel_launch(void* const* d_in, const int* in_sizes, int n_in,
                              void* d_out, int out_size)
{
    const float* tokens   = (const float*)d_in[0];
    const float* traj     = (const float*)d_in[1];
    const float* habs     = (const float*)d_in[2];
    const float* espeed   = (const float*)d_in[3];
    const float* gconf    = (const float*)d_in[4];
    const float* W_ih     = (const float*)d_in[5];
    const float* W_hh     = (const float*)d_in[6];
    const float* b_ih     = (const float*)d_in[7];
    const float* b_hh     = (const float*)d_in[8];
    const float* W_rel    = (const float*)d_in[9];
    const float* W_abs    = (const float*)d_in[10];
    const float* W_g1     = (const float*)d_in[11];
    const float* b_g1     = (const float*)d_in[12];
    const float* W_g2     = (const float*)d_in[13];
    const float* b_g2     = (const float*)d_in[14];
    const float* gamma    = (const float*)d_in[15];
    const float* beta     = (const float*)d_in[16];
    float* out = (float*)d_out;

    // opt-in to >48KB dynamic SMEM (idempotent; not a stream op)
    cudaFuncSetAttribute(lstm_kernel, cudaFuncAttributeMaxDynamicSharedMemorySize, SMEM_A_BYTES);
    cudaFuncSetAttribute(fuse_kernel, cudaFuncAttributeMaxDynamicSharedMemorySize, SMEM_B_BYTES);

    lstm_kernel<<<BN/MT, TPB, SMEM_A_BYTES>>>(traj, W_ih, W_hh, b_ih, b_hh);
    alpha_kernel<<<1, 32>>>(espeed, gconf, W_g1, b_g1, W_g2, b_g2);
    fuse_kernel<<<BN/MT, TPB, SMEM_B_BYTES>>>(tokens, habs, W_rel, W_abs, gamma, beta, out);
}

// round 5
// speedup vs baseline: 3.2389x; 3.2338x over previous
#include <cuda_runtime.h>
#include <cuda_bf16.h>
#include <math.h>
#include <stdint.h>

// ---------------- problem constants ----------------
#define BN      16384
#define HIDN    512
#define G4      2048
#define HLEN    15
#define DIM     1024

// ---------------- LSTM mma.sync config ----------------
#define LTPB    256            // 8 warps
#define LM      64             // rows per CTA
#define NCTA    (BN/LM)        // 256 CTAs
#define BSTR    20             // padded B row stride (floats): conflict-free
#define HSTR    516            // padded h row stride (floats): conflict-free
#define SM_H    (LM*HSTR)              // floats
#define SM_B    (512*BSTR)             // floats per buffer
#define LSMEM   ((SM_H + 2*SM_B)*4)    // 214016 bytes

// fuse kernel config (R1, proven)
#define MT   64
#define TPB  256
#define HS   516
#define SMEM_B_BYTES ((MT*HS + 64*128 + MT*2 + MT*16 + MT*16 + MT + MT)*4)

// ---------------- device scratch ----------------
__device__ float  g_c  [BN * HIDN];
__device__ float  g_hn [BN * HIDN];
__device__ float  g_alpha[32];
__device__ float4 g_Wt [(G4 * HIDN) / 4];   // tiled+permuted W_hh
__device__ float4 g_wihp[G4];               // permuted W_ih rows
__device__ float  g_biasp[G4];              // permuted fused bias

// ---------------- helpers ----------------
__device__ __forceinline__ float sigmoid_f(float x){ return 1.0f/(1.0f+__expf(-x)); }
__device__ __forceinline__ float tanh_f(float x){
    float a=fabsf(x), e=__expf(-2.0f*a); return copysignf((1.0f-e)/(1.0f+e), x);
}
__device__ __forceinline__ uint32_t smem_u32(const void* p){
    uint32_t a; asm("{ .reg .u64 t; cvta.to.shared.u64 t, %1; cvt.u32.u64 %0, t; }":"=r"(a):"l"(p)); return a;
}
__device__ __forceinline__ uint32_t f2tf(float f){
    uint32_t u; asm("cvt.rna.tf32.f32 %0, %1;" : "=r"(u) : "f"(f)); return u;
}
#define CP16(d, s)  asm volatile("cp.async.cg.shared.global [%0], [%1], 16;" :: "r"(d), "l"(s))
#define CP_COMMIT() asm volatile("cp.async.commit_group;" ::: "memory")
#define CP_WAIT0()  asm volatile("cp.async.wait_group 0;" ::: "memory")
#define CP_WAIT1()  asm volatile("cp.async.wait_group 1;" ::: "memory")

#define MMA_TF32(c, a, b0, b1) \
    asm volatile("mma.sync.aligned.m16n8k8.row.col.f32.tf32.tf32.f32 " \
        "{%0,%1,%2,%3}, {%4,%5,%6,%7}, {%8,%9}, {%0,%1,%2,%3};" \
        : "+f"((c)[0]), "+f"((c)[1]), "+f"((c)[2]), "+f"((c)[3]) \
        : "r"((a)[0]), "r"((a)[1]), "r"((a)[2]), "r"((a)[3]), "r"(b0), "r"(b1))

// ---------------------------------------------------------------------------
// reorder: permuted + tiled W_hh, permuted W_ih / fused bias.
// Permuted col w (0..63 within a 64-col warp chunk):
//   j=w/8, q=(w/2)%4, r=w&1;  j<4 -> unit j*4+q gate r(i/f); j>=4 -> unit (j-4)*4+q gate 2+r(g/o)
// so each thread's mma C-fragment (col pairs q*2,q*2+1 of every n-tile) holds
// complete (i,f,g,o) quads: i,f in tile j, g,o in tile j+4.
// Storage: g_Wt[((pass*32+ksl)*512 + n)*16 + kin]  (pass=p/512, n=p%512, k=ksl*16+kin)
// ---------------------------------------------------------------------------
__global__ void reorder_kernel(const float* __restrict__ Whh, const float* __restrict__ Wih,
                               const float* __restrict__ bih, const float* __restrict__ bhh)
{
    int p = blockIdx.x;                   // permuted row 0..2047
    int w = p & 63, chunk = p >> 6;
    int j = w >> 3, qq = (w >> 1) & 3, r = w & 1;
    int gate, ul;
    if (j < 4) { ul = j*4 + qq;     gate = r;     }
    else       { ul = (j-4)*4 + qq; gate = 2 + r; }
    int srow = gate * HIDN + chunk * 16 + ul;
    int pass = p >> 9, n = p & 511;
    const float4* src = (const float4*)(Whh + (size_t)srow * HIDN);
    for (int i = threadIdx.x; i < HIDN/4; i += blockDim.x) {
        int k = i * 4, ksl = k >> 4, kin = k & 15;
        g_Wt[(((pass*32 + ksl)*512 + n)*16 + kin) >> 2] = src[i];
    }
    if (threadIdx.x == 0) {
        g_wihp[p]  = ((const float4*)Wih)[srow];
        g_biasp[p] = bih[srow] + bhh[srow];
    }
}

// ---------------------------------------------------------------------------
// LSTM via mma.sync tf32. 256 CTAs x 256 threads; 64 sequences each.
// Per step: 4 passes of N=512 gate-cols; K=512 in 32 double-buffered 16-slices.
// Warp tile 64x64; A (h) resident in smem; epilogue is shuffle-free.
// ---------------------------------------------------------------------------
__global__ __launch_bounds__(LTPB, 1)
void lstm_mma_kernel(const float* __restrict__ traj)   // (BN,15,4)
{
    extern __shared__ float sm[];
    float* h_s = sm;                       // [64][516]
    float* Bs0 = sm + SM_H;                // [512][20]
    float* Bs1 = Bs0 + SM_B;

    const int tid = threadIdx.x;
    const int lane = tid & 31, warpid = tid >> 5;
    const int q = lane & 3, g8 = lane >> 2;
    const int m0 = blockIdx.x * LM;

    for (int t = 0; t < HLEN; ++t) {
        for (int ncp = 0; ncp < 4; ++ncp) {
            float acc[4][8][4];
            #pragma unroll
            for (int mt = 0; mt < 4; ++mt)
                #pragma unroll
                for (int nt = 0; nt < 8; ++nt)
                    #pragma unroll
                    for (int c = 0; c < 4; ++c) acc[mt][nt][c] = 0.0f;

            if (t > 0) {
                // prologue: stage slice 0 into Bs0
                {
                    const float4* src = g_Wt + (size_t)(ncp*32 + 0) * 512 * 4;
                    #pragma unroll
                    for (int it = 0; it < 8; ++it) {
                        int i = tid + it * LTPB;           // 0..2047
                        int n = i >> 2, kc = i & 3;
                        CP16(smem_u32(Bs0 + n*BSTR + kc*4), src + n*4 + kc);
                    }
                    CP_COMMIT();
                }
                for (int ksl = 0; ksl < 32; ++ksl) {
                    if (ksl < 31) {
                        float* dst = (ksl & 1) ? Bs0 : Bs1;
                        const float4* src = g_Wt + (size_t)(ncp*32 + ksl + 1) * 512 * 4;
                        #pragma unroll
                        for (int it = 0; it < 8; ++it) {
                            int i = tid + it * LTPB;
                            int n = i >> 2, kc = i & 3;
                            CP16(smem_u32(dst + n*BSTR + kc*4), src + n*4 + kc);
                        }
                        CP_COMMIT();
                        CP_WAIT1();
                    } else {
                        CP_WAIT0();
                    }
                    __syncthreads();
                    const float* Bb = (ksl & 1) ? Bs1 : Bs0;
                    #pragma unroll
                    for (int s = 0; s < 2; ++s) {
                        const int kg = ksl*16 + s*8 + q;
                        uint32_t a[4][4];
                        #pragma unroll
                        for (int mt = 0; mt < 4; ++mt) {
                            a[mt][0] = f2tf(h_s[(mt*16 + g8    )*HSTR + kg    ]);
                            a[mt][1] = f2tf(h_s[(mt*16 + g8 + 8)*HSTR + kg    ]);
                            a[mt][2] = f2tf(h_s[(mt*16 + g8    )*HSTR + kg + 4]);
                            a[mt][3] = f2tf(h_s[(mt*16 + g8 + 8)*HSTR + kg + 4]);
                        }
                        #pragma unroll
                        for (int nt = 0; nt < 8; ++nt) {
                            const float* bp = Bb + (warpid*64 + nt*8 + g8)*BSTR + s*8 + q;
                            uint32_t b0 = f2tf(bp[0]);
                            uint32_t b1 = f2tf(bp[4]);
                            #pragma unroll
                            for (int mt = 0; mt < 4; ++mt)
                                MMA_TF32(acc[mt][nt], a[mt], b0, b1);
                        }
                    }
                    __syncthreads();
                }
            }

            // ---- epilogue: this pass covers hidden units [ncp*128, ncp*128+128) ----
            #pragma unroll
            for (int mt = 0; mt < 4; ++mt) {
                #pragma unroll
                for (int half = 0; half < 2; ++half) {
                    const int row = mt*16 + g8 + half*8;
                    const int gr  = m0 + row;
                    const float4 xv = *(const float4*)(traj + ((size_t)gr * HLEN + t) * 4);
                    #pragma unroll
                    for (int j = 0; j < 4; ++j) {
                        const int pi = ncp*512 + warpid*64 + j*8 + q*2;
                        const int pg = pi + 32;
                        float4 wi = g_wihp[pi],   wf = g_wihp[pi+1];
                        float4 wg = g_wihp[pg],   wo = g_wihp[pg+1];
                        float gi = acc[mt][j  ][half*2  ] + g_biasp[pi  ] + xv.x*wi.x + xv.y*wi.y + xv.z*wi.z + xv.w*wi.w;
                        float gf = acc[mt][j  ][half*2+1] + g_biasp[pi+1] + xv.x*wf.x + xv.y*wf.y + xv.z*wf.z + xv.w*wf.w;
                        float gg = acc[mt][j+4][half*2  ] + g_biasp[pg  ] + xv.x*wg.x + xv.y*wg.y + xv.z*wg.z + xv.w*wg.w;
                        float go = acc[mt][j+4][half*2+1] + g_biasp[pg+1] + xv.x*wo.x + xv.y*wo.y + xv.z*wo.z + xv.w*wo.w;
                        const int kg = ncp*128 + warpid*16 + j*4 + q;
                        const size_t idx = (size_t)gr * HIDN + kg;
                        float cp = (t > 0) ? g_c[idx] : 0.0f;
                        float cn = sigmoid_f(gf) * cp + sigmoid_f(gi) * tanh_f(gg);
                        g_c[idx]  = cn;
                        g_hn[idx] = sigmoid_f(go) * tanh_f(cn);
                    }
                }
            }
        }

        if (t < HLEN - 1) {
            __syncthreads();   // all g_hn writes of this step visible
            for (int i = tid; i < (LM*HIDN)/4; i += LTPB) {
                int mrow = i >> 7, k4 = i & 127;
                float4 v = ((const float4*)(g_hn + (size_t)(m0 + mrow)*HIDN))[k4];
                *(float4*)(h_s + mrow*HSTR + k4*4) = v;
            }
            __syncthreads();
        }
    }
}

// ---------------------------------------------------------------------------
__global__ void alpha_kernel(const float* __restrict__ ego_speed, const float* __restrict__ gps_conf,
                             const float* __restrict__ W_g1, const float* __restrict__ b_g1,
                             const float* __restrict__ W_g2, const float* __restrict__ b_g2)
{
    int b = threadIdx.x;
    if (b < 32) {
        float s = ego_speed[b], c = gps_conf[b];
        float acc = b_g2[0];
        #pragma unroll
        for (int h = 0; h < 16; ++h) {
            float t = W_g1[2*h]*s + W_g1[2*h+1]*c + b_g1[h];
            acc += W_g2[h] * fmaxf(t, 0.0f);
        }
        g_alpha[b] = 1.0f / (1.0f + expf(-acc));
    }
}

// ---------------------------------------------------------------------------
// fused projection + blend + residual + LayerNorm (unchanged, proven)
// ---------------------------------------------------------------------------
__global__ __launch_bounds__(TPB, 1)
void fuse_kernel(const float* __restrict__ tokens, const float* __restrict__ habs,
                 const float* __restrict__ W_rel, const float* __restrict__ W_abs,
                 const float* __restrict__ gamma, const float* __restrict__ beta,
                 float* __restrict__ out)
{
    extern __shared__ float sm[];
    float* hs   = sm;
    float* Wt   = sm + MT*HS;
    float* hb   = Wt + 64*128;
    float* redS = hb + MT*2;
    float* redQ = redS + MT*16;
    float* mu_s = redQ + MT*16;
    float* rs_s = mu_s + MT;

    const int tid = threadIdx.x, tx = tid & 15, ty = tid >> 4;
    const int m0 = blockIdx.x * MT;

    for (int i = tid; i < (MT*HIDN)/4; i += TPB) {
        int mm = i >> 7, k4 = i & 127;
        float4 v = ((const float4*)(g_hn + (size_t)(m0 + mm)*HIDN))[k4];
        *(float4*)(hs + mm*HS + k4*4) = v;
    }
    for (int i = tid; i < MT*2; i += TPB) hb[i] = habs[(size_t)m0*2 + i];
    __syncthreads();

    const float al = g_alpha[m0 >> 9], ali = 1.0f - al;
    float rsum[4] = {0,0,0,0}, rq[4] = {0,0,0,0};

    for (int ch = 0; ch < 8; ++ch) {
        const int jb = ch * 128;
        float acc[4][8];
        #pragma unroll
        for (int r = 0; r < 4; ++r)
            #pragma unroll
            for (int cc = 0; cc < 8; ++cc) acc[r][cc] = 0.0f;

        for (int kb = 0; kb < HIDN; kb += 64) {
            __syncthreads();
            #pragma unroll
            for (int it = 0; it < 4; ++it) {
                int s = tid + it * TPB;
                int c = s & 127, sub = s >> 7;
                const float* src = W_rel + (size_t)(jb + c)*HIDN + kb + sub*8;
                float4 w0 = *(const float4*)src;
                float4 w1 = *(const float4*)(src + 4);
                float* dst = Wt + (sub*8)*128 + c;
                dst[0]=w0.x; dst[128]=w0.y; dst[256]=w0.z; dst[384]=w0.w;
                dst[512]=w1.x; dst[640]=w1.y; dst[768]=w1.z; dst[896]=w1.w;
            }
            __syncthreads();
            #pragma unroll 4
            for (int kk = 0; kk < 64; ++kk) {
                float a[4];
                #pragma unroll
                for (int r = 0; r < 4; ++r) a[r] = hs[(ty*4 + r)*HS + kb + kk];
                float4 b0 = *(float4*)(Wt + kk*128 + tx*8);
                float4 b1 = *(float4*)(Wt + kk*128 + tx*8 + 4);
                #pragma unroll
                for (int r = 0; r < 4; ++r) {
                    acc[r][0] += a[r]*b0.x; acc[r][1] += a[r]*b0.y;
                    acc[r][2] += a[r]*b0.z; acc[r][3] += a[r]*b0.w;
                    acc[r][4] += a[r]*b1.x; acc[r][5] += a[r]*b1.y;
                    acc[r][6] += a[r]*b1.z; acc[r][7] += a[r]*b1.w;
                }
            }
        }

        #pragma unroll
        for (int r = 0; r < 4; ++r) {
            int mm = ty*4 + r, R = m0 + mm;
            float h0 = hb[mm*2], h1 = hb[mm*2+1];
            const int j0 = jb + tx*8;
            float4 t0 = *(const float4*)(tokens + (size_t)R*DIM + j0);
            float4 t1 = *(const float4*)(tokens + (size_t)R*DIM + j0 + 4);
            float tk[8] = {t0.x,t0.y,t0.z,t0.w,t1.x,t1.y,t1.z,t1.w};
            float xvv[8];
            #pragma unroll
            for (int cc = 0; cc < 8; ++cc) {
                int j = j0 + cc;
                float2 wa = ((const float2*)W_abs)[j];
                float x = tk[cc] + al*acc[r][cc] + ali*(h0*wa.x + h1*wa.y);
                xvv[cc] = x; rsum[r] += x; rq[r] += x*x;
            }
            *(float4*)(out + (size_t)R*DIM + j0)     = make_float4(xvv[0],xvv[1],xvv[2],xvv[3]);
            *(float4*)(out + (size_t)R*DIM + j0 + 4) = make_float4(xvv[4],xvv[5],xvv[6],xvv[7]);
        }
    }

    __syncthreads();
    #pragma unroll
    for (int r = 0; r < 4; ++r) {
        redS[(ty*4 + r)*16 + tx] = rsum[r];
        redQ[(ty*4 + r)*16 + tx] = rq[r];
    }
    __syncthreads();
    if (tid < MT) {
        float s = 0.0f, qq = 0.0f;
        #pragma unroll
        for (int i = 0; i < 16; ++i) { s += redS[tid*16 + i]; qq += redQ[tid*16 + i]; }
        float mu = s * (1.0f/DIM);
        float var = qq * (1.0f/DIM) - mu*mu;
        mu_s[tid] = mu; rs_s[tid] = rsqrtf(var + 1e-5f);
    }
    __syncthreads();
    for (int i = tid; i < (MT*DIM)/4; i += TPB) {
        int mm = i >> 8, j4 = i & 255;
        float4 v = ((float4*)(out + (size_t)(m0 + mm)*DIM))[j4];
        float4 g = ((const float4*)gamma)[j4];
        float4 b = ((const float4*)beta)[j4];
        float mu = mu_s[mm], rr = rs_s[mm];
        v.x = (v.x - mu)*rr*g.x + b.x;
        v.y = (v.y - mu)*rr*g.y + b.y;
        v.z = (v.z - mu)*rr*g.z + b.z;
        v.w = (v.w - mu)*rr*g.w + b.w;
        ((float4*)(out + (size_t)(m0 + mm)*DIM))[j4] = v;
    }
}

// ---------------------------------------------------------------------------
extern "C" void kernel_launch(void* const* d_in, const int* in_sizes, int n_in,
                              void* d_out, int out_size)
{
    const float* tokens = (const float*)d_in[0];
    const float* traj   = (const float*)d_in[1];
    const float* habs   = (const float*)d_in[2];
    const float* espeed = (const float*)d_in[3];
    const float* gconf  = (const float*)d_in[4];
    const float* W_ih   = (const float*)d_in[5];
    const float* W_hh   = (const float*)d_in[6];
    const float* b_ih   = (const float*)d_in[7];
    const float* b_hh   = (const float*)d_in[8];
    const float* W_rel  = (const float*)d_in[9];
    const float* W_abs  = (const float*)d_in[10];
    const float* W_g1   = (const float*)d_in[11];
    const float* b_g1   = (const float*)d_in[12];
    const float* W_g2   = (const float*)d_in[13];
    const float* b_g2   = (const float*)d_in[14];
    const float* gamma  = (const float*)d_in[15];
    const float* beta   = (const float*)d_in[16];
    float* out = (float*)d_out;

    cudaFuncSetAttribute(lstm_mma_kernel, cudaFuncAttributeMaxDynamicSharedMemorySize, LSMEM);
    cudaFuncSetAttribute(fuse_kernel,     cudaFuncAttributeMaxDynamicSharedMemorySize, SMEM_B_BYTES);

    reorder_kernel<<<G4, 128>>>(W_hh, W_ih, b_ih, b_hh);
    lstm_mma_kernel<<<NCTA, LTPB, LSMEM>>>(traj);
    alpha_kernel<<<1, 32>>>(espeed, gconf, W_g1, b_g1, W_g2, b_g2);
    fuse_kernel<<<BN/MT, TPB, SMEM_B_BYTES>>>(tokens, habs, W_rel, W_abs, gamma, beta, out);
}

// round 6
// speedup vs baseline: 6.4954x; 2.0054x over previous
#include <cuda_runtime.h>
#include <cuda_bf16.h>
#include <math.h>
#include <stdint.h>

// ---------------- problem constants ----------------
#define BN      16384
#define HIDN    512
#define G4      2048
#define HLEN    15
#define DIM     1024

// ---------------- LSTM mma bf16 config ----------------
#define LTPB    256            // 8 warps
#define LM      64             // rows per CTA
#define NCTA    (BN/LM)        // 256 CTAs
#define HSW     260            // h row stride in u32 words (=520 bf16): bank-safe (260 % 32 == 4)

// smem layout (bytes)
#define OFF_H0   0
#define OFF_H1   66560                  // 64*520*2
#define OFF_TRJ  133120                 // 64*60*4  = 15360
#define OFF_WIH  148480                 // 2048*16  = 32768
#define OFF_BIAS 181248                 // 2048*4   = 8192
#define LSMEM    189440

// fuse kernel config (proven)
#define MT   64
#define TPB  256
#define HS   516
#define SMEM_B_BYTES ((MT*HS + 64*128 + MT*2 + MT*16 + MT*16 + MT + MT)*4)

// ---------------- device scratch ----------------
__device__ float    g_c  [BN * HIDN];      // LSTM cell state (fp32, L2-resident)
__device__ float    g_hn [BN * HIDN];      // final hidden (fp32) for fuse
__device__ float    g_alpha[32];
__device__ uint32_t g_Wf [G4 * HIDN / 2];  // W_hh bf16x2 in mma fragment order
__device__ float4   g_wihp[G4];            // permuted W_ih rows
__device__ float    g_biasp[G4];           // permuted fused bias

// ---------------- helpers ----------------
__device__ __forceinline__ float sigmoid_f(float x){ return 1.0f/(1.0f+__expf(-x)); }
__device__ __forceinline__ float tanh_f(float x){
    float a=fabsf(x), e=__expf(-2.0f*a); return copysignf((1.0f-e)/(1.0f+e), x);
}
#define MMA_BF16(c, a, b0, b1) \
    asm volatile("mma.sync.aligned.m16n8k16.row.col.f32.bf16.bf16.f32 " \
        "{%0,%1,%2,%3}, {%4,%5,%6,%7}, {%8,%9}, {%0,%1,%2,%3};" \
        : "+f"((c)[0]), "+f"((c)[1]), "+f"((c)[2]), "+f"((c)[3]) \
        : "r"((a)[0]), "r"((a)[1]), "r"((a)[2]), "r"((a)[3]), "r"(b0), "r"(b1))

// ---------------------------------------------------------------------------
// reorder: W_hh -> bf16x2 fragment-order g_Wf; permuted W_ih / fused bias.
// Permuted col n (0..2047): w=(n>>6)&7 chunk col cw=n&63: j=cw>>3, q=(cw>>1)&3,
// r=cw&1; j<4 -> unit j*4+q gate r(i/f); j>=4 -> unit (j-4)*4+q gate 2+r(g/o);
// unit index = chunk*16+ul with chunk=n>>6.  (identical to R4 permutation)
// Fragment storage (u32): (((((pass*32+ksl)*8+w)*8+nt)*32+lane)*2+j)
//   pass=n>>9, nt=(n>>3)&7, lane=(n&7)*4+q_k, j=(k&15)>>3, q_k=((k&7)>>1)
//   value = bf16x2( W[srow][k_even], W[srow][k_even+1] )
// ---------------------------------------------------------------------------
__global__ void reorder_kernel(const float* __restrict__ Whh, const float* __restrict__ Wih,
                               const float* __restrict__ bih, const float* __restrict__ bhh)
{
    int n = blockIdx.x;                   // permuted col 0..2047
    int cw = n & 63, chunk = n >> 6;
    int j = cw >> 3, qq = (cw >> 1) & 3, r = cw & 1;
    int gate, ul;
    if (j < 4) { ul = j*4 + qq;     gate = r;     }
    else       { ul = (j-4)*4 + qq; gate = 2 + r; }
    int srow = gate * HIDN + chunk * 16 + ul;

    const float* src = Whh + (size_t)srow * HIDN;
    int pass = n >> 9, w = (n >> 6) & 7, nt = (n >> 3) & 7, g8 = n & 7;

    for (int k2 = threadIdx.x; k2 < HIDN/2; k2 += blockDim.x) {
        int k = k2 * 2;
        int ksl = k >> 4, kin = k & 15;
        int jj = kin >> 3, qk = (kin >> 1) & 3;
        __nv_bfloat162 p = __floats2bfloat162_rn(src[k], src[k+1]);
        uint32_t u; memcpy(&u, &p, 4);
        int lane = g8*4 + qk;
        size_t idx = ((((((size_t)pass*32 + ksl)*8 + w)*8 + nt)*32 + lane)*2 + jj);
        g_Wf[idx] = u;
    }
    if (threadIdx.x == 0) {
        g_wihp[n]  = ((const float4*)Wih)[srow];
        g_biasp[n] = bih[srow] + bhh[srow];
    }
}

// ---------------------------------------------------------------------------
// LSTM via mma.sync bf16 m16n8k16. 256 CTAs x 256 threads; 64 rows each.
// B streamed from global in fragment order (no B smem, no per-slice syncs).
// h double-buffered bf16 in smem; ONE barrier per timestep.
// ---------------------------------------------------------------------------
__global__ __launch_bounds__(LTPB, 1)
void lstm_mma_kernel(const float* __restrict__ traj)   // (BN,15,4)
{
    extern __shared__ char smem[];
    float*  trj    = (float*) (smem + OFF_TRJ);   // [64][60]
    float4* wih_s  = (float4*)(smem + OFF_WIH);   // [2048]
    float*  bias_s = (float*) (smem + OFF_BIAS);  // [2048]

    const int tid = threadIdx.x;
    const int lane = tid & 31, warpid = tid >> 5;
    const int q = lane & 3, g8 = lane >> 2;
    const int m0 = blockIdx.x * LM;

    // one-time smem loads
    for (int i = tid; i < (LM*HLEN*4)/4; i += LTPB)
        ((float4*)trj)[i] = ((const float4*)(traj + (size_t)m0 * (HLEN*4)))[i];
    for (int i = tid; i < G4; i += LTPB) {
        wih_s[i]  = g_wihp[i];
        bias_s[i] = g_biasp[i];
    }
    __syncthreads();

    const uint2* __restrict__ Wf64 = (const uint2*)g_Wf;

    for (int t = 0; t < HLEN; ++t) {
        const uint32_t* hcur = (const uint32_t*)(smem + ((t & 1) ? OFF_H1 : OFF_H0));
        __nv_bfloat16*  hnxt = (__nv_bfloat16*)(smem + ((t & 1) ? OFF_H0 : OFF_H1));

        for (int ncp = 0; ncp < 4; ++ncp) {
            float acc[4][8][4];
            #pragma unroll
            for (int mt = 0; mt < 4; ++mt)
                #pragma unroll
                for (int nt = 0; nt < 8; ++nt)
                    #pragma unroll
                    for (int c = 0; c < 4; ++c) acc[mt][nt][c] = 0.0f;

            if (t > 0) {
                // base: (((ncp*32 + ksl)*8 + warpid)*8 + nt)*32 + lane   [u64 units]
                const uint2* Bp = Wf64 + ((((size_t)ncp*32)*8 + warpid)*8)*32 + lane;
                uint2 bc[8], bn[8];
                #pragma unroll
                for (int nt = 0; nt < 8; ++nt) bc[nt] = Bp[nt*32];

                for (int ksl = 0; ksl < 32; ++ksl) {
                    if (ksl < 31) {
                        const uint2* Bn = Bp + (size_t)(ksl + 1) * 2048;
                        #pragma unroll
                        for (int nt = 0; nt < 8; ++nt) bn[nt] = Bn[nt*32];
                    }
                    // A fragments from smem bf16 (bank-conflict-free)
                    uint32_t a[4][4];
                    const int kw = ksl * 8 + q;       // u32 word offset in row
                    #pragma unroll
                    for (int mt = 0; mt < 4; ++mt) {
                        int r0 = (mt*16 + g8) * HSW + kw;
                        a[mt][0] = hcur[r0];
                        a[mt][1] = hcur[r0 + 8*HSW];
                        a[mt][2] = hcur[r0 + 4];
                        a[mt][3] = hcur[r0 + 8*HSW + 4];
                    }
                    #pragma unroll
                    for (int nt = 0; nt < 8; ++nt) {
                        #pragma unroll
                        for (int mt = 0; mt < 4; ++mt)
                            MMA_BF16(acc[mt][nt], a[mt], bc[nt].x, bc[nt].y);
                    }
                    #pragma unroll
                    for (int nt = 0; nt < 8; ++nt) bc[nt] = bn[nt];
                }
            }

            // ---- epilogue: pass covers hidden units [ncp*128, ncp*128+128) ----
            #pragma unroll
            for (int mt = 0; mt < 4; ++mt) {
                #pragma unroll
                for (int half = 0; half < 2; ++half) {
                    const int row = mt*16 + g8 + half*8;
                    const int gr  = m0 + row;
                    const float4 xv = *(const float4*)(trj + row*60 + t*4);
                    #pragma unroll
                    for (int j = 0; j < 4; ++j) {
                        const int pi = ncp*512 + warpid*64 + j*8 + q*2;
                        const int pg = pi + 32;
                        float4 wi = wih_s[pi],   wf = wih_s[pi+1];
                        float4 wg = wih_s[pg],   wo = wih_s[pg+1];
                        float gi = acc[mt][j  ][half*2  ] + bias_s[pi  ] + xv.x*wi.x + xv.y*wi.y + xv.z*wi.z + xv.w*wi.w;
                        float gf = acc[mt][j  ][half*2+1] + bias_s[pi+1] + xv.x*wf.x + xv.y*wf.y + xv.z*wf.z + xv.w*wf.w;
                        float gg = acc[mt][j+4][half*2  ] + bias_s[pg  ] + xv.x*wg.x + xv.y*wg.y + xv.z*wg.z + xv.w*wg.w;
                        float go = acc[mt][j+4][half*2+1] + bias_s[pg+1] + xv.x*wo.x + xv.y*wo.y + xv.z*wo.z + xv.w*wo.w;
                        const int kg = ncp*128 + warpid*16 + j*4 + q;
                        const size_t idx = (size_t)gr * HIDN + kg;
                        float cp = (t > 0) ? g_c[idx] : 0.0f;
                        float cn = sigmoid_f(gf) * cp + sigmoid_f(gi) * tanh_f(gg);
                        g_c[idx] = cn;
                        float hn = sigmoid_f(go) * tanh_f(cn);
                        hnxt[row*520 + kg] = __float2bfloat16_rn(hn);
                        if (t == HLEN - 1) g_hn[idx] = hn;
                    }
                }
            }
        }
        __syncthreads();   // h_t complete + all h_{t-1} reads done
    }
}

// ---------------------------------------------------------------------------
__global__ void alpha_kernel(const float* __restrict__ ego_speed, const float* __restrict__ gps_conf,
                             const float* __restrict__ W_g1, const float* __restrict__ b_g1,
                             const float* __restrict__ W_g2, const float* __restrict__ b_g2)
{
    int b = threadIdx.x;
    if (b < 32) {
        float s = ego_speed[b], c = gps_conf[b];
        float acc = b_g2[0];
        #pragma unroll
        for (int h = 0; h < 16; ++h) {
            float t = W_g1[2*h]*s + W_g1[2*h+1]*c + b_g1[h];
            acc += W_g2[h] * fmaxf(t, 0.0f);
        }
        g_alpha[b] = 1.0f / (1.0f + expf(-acc));
    }
}

// ---------------------------------------------------------------------------
// fused projection + blend + residual + LayerNorm (unchanged, proven)
// ---------------------------------------------------------------------------
__global__ __launch_bounds__(TPB, 1)
void fuse_kernel(const float* __restrict__ tokens, const float* __restrict__ habs,
                 const float* __restrict__ W_rel, const float* __restrict__ W_abs,
                 const float* __restrict__ gamma, const float* __restrict__ beta,
                 float* __restrict__ out)
{
    extern __shared__ float sm[];
    float* hs   = sm;
    float* Wt   = sm + MT*HS;
    float* hb   = Wt + 64*128;
    float* redS = hb + MT*2;
    float* redQ = redS + MT*16;
    float* mu_s = redQ + MT*16;
    float* rs_s = mu_s + MT;

    const int tid = threadIdx.x, tx = tid & 15, ty = tid >> 4;
    const int m0 = blockIdx.x * MT;

    for (int i = tid; i < (MT*HIDN)/4; i += TPB) {
        int mm = i >> 7, k4 = i & 127;
        float4 v = ((const float4*)(g_hn + (size_t)(m0 + mm)*HIDN))[k4];
        *(float4*)(hs + mm*HS + k4*4) = v;
    }
    for (int i = tid; i < MT*2; i += TPB) hb[i] = habs[(size_t)m0*2 + i];
    __syncthreads();

    const float al = g_alpha[m0 >> 9], ali = 1.0f - al;
    float rsum[4] = {0,0,0,0}, rq[4] = {0,0,0,0};

    for (int ch = 0; ch < 8; ++ch) {
        const int jb = ch * 128;
        float acc[4][8];
        #pragma unroll
        for (int r = 0; r < 4; ++r)
            #pragma unroll
            for (int cc = 0; cc < 8; ++cc) acc[r][cc] = 0.0f;

        for (int kb = 0; kb < HIDN; kb += 64) {
            __syncthreads();
            #pragma unroll
            for (int it = 0; it < 4; ++it) {
                int s = tid + it * TPB;
                int c = s & 127, sub = s >> 7;
                const float* src = W_rel + (size_t)(jb + c)*HIDN + kb + sub*8;
                float4 w0 = *(const float4*)src;
                float4 w1 = *(const float4*)(src + 4);
                float* dst = Wt + (sub*8)*128 + c;
                dst[0]=w0.x; dst[128]=w0.y; dst[256]=w0.z; dst[384]=w0.w;
                dst[512]=w1.x; dst[640]=w1.y; dst[768]=w1.z; dst[896]=w1.w;
            }
            __syncthreads();
            #pragma unroll 4
            for (int kk = 0; kk < 64; ++kk) {
                float a[4];
                #pragma unroll
                for (int r = 0; r < 4; ++r) a[r] = hs[(ty*4 + r)*HS + kb + kk];
                float4 b0 = *(float4*)(Wt + kk*128 + tx*8);
                float4 b1 = *(float4*)(Wt + kk*128 + tx*8 + 4);
                #pragma unroll
                for (int r = 0; r < 4; ++r) {
                    acc[r][0] += a[r]*b0.x; acc[r][1] += a[r]*b0.y;
                    acc[r][2] += a[r]*b0.z; acc[r][3] += a[r]*b0.w;
                    acc[r][4] += a[r]*b1.x; acc[r][5] += a[r]*b1.y;
                    acc[r][6] += a[r]*b1.z; acc[r][7] += a[r]*b1.w;
                }
            }
        }

        #pragma unroll
        for (int r = 0; r < 4; ++r) {
            int mm = ty*4 + r, R = m0 + mm;
            float h0 = hb[mm*2], h1 = hb[mm*2+1];
            const int j0 = jb + tx*8;
            float4 t0 = *(const float4*)(tokens + (size_t)R*DIM + j0);
            float4 t1 = *(const float4*)(tokens + (size_t)R*DIM + j0 + 4);
            float tk[8] = {t0.x,t0.y,t0.z,t0.w,t1.x,t1.y,t1.z,t1.w};
            float xvv[8];
            #pragma unroll
            for (int cc = 0; cc < 8; ++cc) {
                int j = j0 + cc;
                float2 wa = ((const float2*)W_abs)[j];
                float x = tk[cc] + al*acc[r][cc] + ali*(h0*wa.x + h1*wa.y);
                xvv[cc] = x; rsum[r] += x; rq[r] += x*x;
            }
            *(float4*)(out + (size_t)R*DIM + j0)     = make_float4(xvv[0],xvv[1],xvv[2],xvv[3]);
            *(float4*)(out + (size_t)R*DIM + j0 + 4) = make_float4(xvv[4],xvv[5],xvv[6],xvv[7]);
        }
    }

    __syncthreads();
    #pragma unroll
    for (int r = 0; r < 4; ++r) {
        redS[(ty*4 + r)*16 + tx] = rsum[r];
        redQ[(ty*4 + r)*16 + tx] = rq[r];
    }
    __syncthreads();
    if (tid < MT) {
        float s = 0.0f, qq = 0.0f;
        #pragma unroll
        for (int i = 0; i < 16; ++i) { s += redS[tid*16 + i]; qq += redQ[tid*16 + i]; }
        float mu = s * (1.0f/DIM);
        float var = qq * (1.0f/DIM) - mu*mu;
        mu_s[tid] = mu; rs_s[tid] = rsqrtf(var + 1e-5f);
    }
    __syncthreads();
    for (int i = tid; i < (MT*DIM)/4; i += TPB) {
        int mm = i >> 8, j4 = i & 255;
        float4 v = ((float4*)(out + (size_t)(m0 + mm)*DIM))[j4];
        float4 g = ((const float4*)gamma)[j4];
        float4 b = ((const float4*)beta)[j4];
        float mu = mu_s[mm], rr = rs_s[mm];
        v.x = (v.x - mu)*rr*g.x + b.x;
        v.y = (v.y - mu)*rr*g.y + b.y;
        v.z = (v.z - mu)*rr*g.z + b.z;
        v.w = (v.w - mu)*rr*g.w + b.w;
        ((float4*)(out + (size_t)(m0 + mm)*DIM))[j4] = v;
    }
}

// ---------------------------------------------------------------------------
extern "C" void kernel_launch(void* const* d_in, const int* in_sizes, int n_in,
                              void* d_out, int out_size)
{
    const float* tokens = (const float*)d_in[0];
    const float* traj   = (const float*)d_in[1];
    const float* habs   = (const float*)d_in[2];
    const float* espeed = (const float*)d_in[3];
    const float* gconf  = (const float*)d_in[4];
    const float* W_ih   = (const float*)d_in[5];
    const float* W_hh   = (const float*)d_in[6];
    const float* b_ih   = (const float*)d_in[7];
    const float* b_hh   = (const float*)d_in[8];
    const float* W_rel  = (const float*)d_in[9];
    const float* W_abs  = (const float*)d_in[10];
    const float* W_g1   = (const float*)d_in[11];
    const float* b_g1   = (const float*)d_in[12];
    const float* W_g2   = (const float*)d_in[13];
    const float* b_g2   = (const float*)d_in[14];
    const float* gamma  = (const float*)d_in[15];
    const float* beta   = (const float*)d_in[16];
    float* out = (float*)d_out;

    cudaFuncSetAttribute(lstm_mma_kernel, cudaFuncAttributeMaxDynamicSharedMemorySize, LSMEM);
    cudaFuncSetAttribute(fuse_kernel,     cudaFuncAttributeMaxDynamicSharedMemorySize, SMEM_B_BYTES);

    reorder_kernel<<<G4, 128>>>(W_hh, W_ih, b_ih, b_hh);
    lstm_mma_kernel<<<NCTA, LTPB, LSMEM>>>(traj);
    alpha_kernel<<<1, 32>>>(espeed, gconf, W_g1, b_g1, W_g2, b_g2);
    fuse_kernel<<<BN/MT, TPB, SMEM_B_BYTES>>>(tokens, habs, W_rel, W_abs, gamma, beta, out);
}

// round 7
// speedup vs baseline: 8.2188x; 1.2653x over previous
#include <cuda_runtime.h>
#include <cuda_bf16.h>
#include <math.h>
#include <stdint.h>
#include <string.h>

// ---------------- problem constants ----------------
#define BN      16384
#define HIDN    512
#define G4      2048
#define HLEN    15
#define DIM     1024

// ---------------- LSTM mma bf16 config ----------------
#define LTPB    256            // 8 warps
#define LM      64             // rows per CTA
#define NCTA    (BN/LM)        // 256 CTAs
#define HSW     260            // h row stride in u32 words (=520 bf16)

// LSTM smem layout (bytes)
#define OFF_H0   0
#define OFF_H1   66560
#define OFF_TRJ  133120
#define OFF_WIH  148480
#define OFF_BIAS 181248
#define LSMEM    189440

// fuse_mma smem layout (bytes)
#define FO_HS    0              // 64*260 u32  = 66560
#define FO_HB    66560          // 64*2 f32    = 512
#define FO_RS    67072          // 64*32 f32   = 8192
#define FO_RQ    75264          // 8192
#define FO_MU    83456          // 256
#define FO_RV    83712          // 256
#define FSMEM    83968

// ---------------- device scratch ----------------
__device__ float    g_c  [BN * HIDN];      // LSTM cell state
__device__ float    g_hn [BN * HIDN];      // final hidden (fp32)
__device__ float    g_alpha[32];
__device__ uint32_t g_Wf [G4 * HIDN / 2];  // W_hh bf16x2 fragment order
__device__ uint32_t g_Wrf[DIM * HIDN / 2]; // W_rel bf16x2 fragment order
__device__ float4   g_wihp[G4];
__device__ float    g_biasp[G4];

// ---------------- helpers ----------------
__device__ __forceinline__ float sigmoid_f(float x){ return 1.0f/(1.0f+__expf(-x)); }
__device__ __forceinline__ float tanh_f(float x){
    float a=fabsf(x), e=__expf(-2.0f*a); return copysignf((1.0f-e)/(1.0f+e), x);
}
#define MMA_BF16(c, a, b0, b1) \
    asm volatile("mma.sync.aligned.m16n8k16.row.col.f32.bf16.bf16.f32 " \
        "{%0,%1,%2,%3}, {%4,%5,%6,%7}, {%8,%9}, {%0,%1,%2,%3};" \
        : "+f"((c)[0]), "+f"((c)[1]), "+f"((c)[2]), "+f"((c)[3]) \
        : "r"((a)[0]), "r"((a)[1]), "r"((a)[2]), "r"((a)[3]), "r"(b0), "r"(b1))

// ---------------------------------------------------------------------------
// reorder: W_hh -> g_Wf (gate-permuted, proven R6); W_rel -> g_Wrf (natural).
// blocks 0..2047 : W_hh cols; blocks 2048..3071 : W_rel cols.
// ---------------------------------------------------------------------------
__global__ void reorder_kernel(const float* __restrict__ Whh, const float* __restrict__ Wih,
                               const float* __restrict__ bih, const float* __restrict__ bhh,
                               const float* __restrict__ Wrel)
{
    if (blockIdx.x < G4) {
        int n = blockIdx.x;
        int cw = n & 63, chunk = n >> 6;
        int j = cw >> 3, qq = (cw >> 1) & 3, r = cw & 1;
        int gate, ul;
        if (j < 4) { ul = j*4 + qq;     gate = r;     }
        else       { ul = (j-4)*4 + qq; gate = 2 + r; }
        int srow = gate * HIDN + chunk * 16 + ul;

        const float* src = Whh + (size_t)srow * HIDN;
        int pass = n >> 9, w = (n >> 6) & 7, nt = (n >> 3) & 7, g8 = n & 7;

        for (int k2 = threadIdx.x; k2 < HIDN/2; k2 += blockDim.x) {
            int k = k2 * 2;
            int ksl = k >> 4, kin = k & 15;
            int jj = kin >> 3, qk = (kin >> 1) & 3;
            __nv_bfloat162 p = __floats2bfloat162_rn(src[k], src[k+1]);
            uint32_t u; memcpy(&u, &p, 4);
            int lane = g8*4 + qk;
            size_t idx = ((((((size_t)pass*32 + ksl)*8 + w)*8 + nt)*32 + lane)*2 + jj);
            g_Wf[idx] = u;
        }
        if (threadIdx.x == 0) {
            g_wihp[n]  = ((const float4*)Wih)[srow];
            g_biasp[n] = bih[srow] + bhh[srow];
        }
    } else {
        int n = blockIdx.x - G4;            // output col 0..1023
        const float* src = Wrel + (size_t)n * HIDN;
        int w = n >> 7, ch = (n >> 6) & 1, nt = (n >> 3) & 7, g8 = n & 7;
        for (int k2 = threadIdx.x; k2 < HIDN/2; k2 += blockDim.x) {
            int k = k2 * 2;
            int ksl = k >> 4, kin = k & 15;
            int jj = kin >> 3, qk = (kin >> 1) & 3;
            __nv_bfloat162 p = __floats2bfloat162_rn(src[k], src[k+1]);
            uint32_t u; memcpy(&u, &p, 4);
            int lane = g8*4 + qk;
            size_t idx = ((((((size_t)(w*2 + ch))*32 + ksl)*8 + nt)*32 + lane)*2 + jj);
            g_Wrf[idx] = u;
        }
    }
}

// ---------------------------------------------------------------------------
// LSTM via mma.sync bf16 (unchanged from R6 — proven at 2.65 ms)
// ---------------------------------------------------------------------------
__global__ __launch_bounds__(LTPB, 1)
void lstm_mma_kernel(const float* __restrict__ traj)
{
    extern __shared__ char smem[];
    float*  trj    = (float*) (smem + OFF_TRJ);
    float4* wih_s  = (float4*)(smem + OFF_WIH);
    float*  bias_s = (float*) (smem + OFF_BIAS);

    const int tid = threadIdx.x;
    const int lane = tid & 31, warpid = tid >> 5;
    const int q = lane & 3, g8 = lane >> 2;
    const int m0 = blockIdx.x * LM;

    for (int i = tid; i < (LM*HLEN*4)/4; i += LTPB)
        ((float4*)trj)[i] = ((const float4*)(traj + (size_t)m0 * (HLEN*4)))[i];
    for (int i = tid; i < G4; i += LTPB) {
        wih_s[i]  = g_wihp[i];
        bias_s[i] = g_biasp[i];
    }
    __syncthreads();

    const uint2* __restrict__ Wf64 = (const uint2*)g_Wf;

    for (int t = 0; t < HLEN; ++t) {
        const uint32_t* hcur = (const uint32_t*)(smem + ((t & 1) ? OFF_H1 : OFF_H0));
        __nv_bfloat16*  hnxt = (__nv_bfloat16*)(smem + ((t & 1) ? OFF_H0 : OFF_H1));

        for (int ncp = 0; ncp < 4; ++ncp) {
            float acc[4][8][4];
            #pragma unroll
            for (int mt = 0; mt < 4; ++mt)
                #pragma unroll
                for (int nt = 0; nt < 8; ++nt)
                    #pragma unroll
                    for (int c = 0; c < 4; ++c) acc[mt][nt][c] = 0.0f;

            if (t > 0) {
                const uint2* Bp = Wf64 + ((((size_t)ncp*32)*8 + warpid)*8)*32 + lane;
                uint2 bc[8], bn[8];
                #pragma unroll
                for (int nt = 0; nt < 8; ++nt) bc[nt] = Bp[nt*32];

                for (int ksl = 0; ksl < 32; ++ksl) {
                    if (ksl < 31) {
                        const uint2* Bn = Bp + (size_t)(ksl + 1) * 2048;
                        #pragma unroll
                        for (int nt = 0; nt < 8; ++nt) bn[nt] = Bn[nt*32];
                    }
                    uint32_t a[4][4];
                    const int kw = ksl * 8 + q;
                    #pragma unroll
                    for (int mt = 0; mt < 4; ++mt) {
                        int r0 = (mt*16 + g8) * HSW + kw;
                        a[mt][0] = hcur[r0];
                        a[mt][1] = hcur[r0 + 8*HSW];
                        a[mt][2] = hcur[r0 + 4];
                        a[mt][3] = hcur[r0 + 8*HSW + 4];
                    }
                    #pragma unroll
                    for (int nt = 0; nt < 8; ++nt) {
                        #pragma unroll
                        for (int mt = 0; mt < 4; ++mt)
                            MMA_BF16(acc[mt][nt], a[mt], bc[nt].x, bc[nt].y);
                    }
                    #pragma unroll
                    for (int nt = 0; nt < 8; ++nt) bc[nt] = bn[nt];
                }
            }

            #pragma unroll
            for (int mt = 0; mt < 4; ++mt) {
                #pragma unroll
                for (int half = 0; half < 2; ++half) {
                    const int row = mt*16 + g8 + half*8;
                    const int gr  = m0 + row;
                    const float4 xv = *(const float4*)(trj + row*60 + t*4);
                    #pragma unroll
                    for (int j = 0; j < 4; ++j) {
                        const int pi = ncp*512 + warpid*64 + j*8 + q*2;
                        const int pg = pi + 32;
                        float4 wi = wih_s[pi],   wf = wih_s[pi+1];
                        float4 wg = wih_s[pg],   wo = wih_s[pg+1];
                        float gi = acc[mt][j  ][half*2  ] + bias_s[pi  ] + xv.x*wi.x + xv.y*wi.y + xv.z*wi.z + xv.w*wi.w;
                        float gf = acc[mt][j  ][half*2+1] + bias_s[pi+1] + xv.x*wf.x + xv.y*wf.y + xv.z*wf.z + xv.w*wf.w;
                        float gg = acc[mt][j+4][half*2  ] + bias_s[pg  ] + xv.x*wg.x + xv.y*wg.y + xv.z*wg.z + xv.w*wg.w;
                        float go = acc[mt][j+4][half*2+1] + bias_s[pg+1] + xv.x*wo.x + xv.y*wo.y + xv.z*wo.z + xv.w*wo.w;
                        const int kg = ncp*128 + warpid*16 + j*4 + q;
                        const size_t idx = (size_t)gr * HIDN + kg;
                        float cp = (t > 0) ? g_c[idx] : 0.0f;
                        float cn = sigmoid_f(gf) * cp + sigmoid_f(gi) * tanh_f(gg);
                        g_c[idx] = cn;
                        float hn = sigmoid_f(go) * tanh_f(cn);
                        hnxt[row*520 + kg] = __float2bfloat16_rn(hn);
                        if (t == HLEN - 1) g_hn[idx] = hn;
                    }
                }
            }
        }
        __syncthreads();
    }
}

// ---------------------------------------------------------------------------
__global__ void alpha_kernel(const float* __restrict__ ego_speed, const float* __restrict__ gps_conf,
                             const float* __restrict__ W_g1, const float* __restrict__ b_g1,
                             const float* __restrict__ W_g2, const float* __restrict__ b_g2)
{
    int b = threadIdx.x;
    if (b < 32) {
        float s = ego_speed[b], c = gps_conf[b];
        float acc = b_g2[0];
        #pragma unroll
        for (int h = 0; h < 16; ++h) {
            float t = W_g1[2*h]*s + W_g1[2*h+1]*c + b_g1[h];
            acc += W_g2[h] * fmaxf(t, 0.0f);
        }
        g_alpha[b] = 1.0f / (1.0f + expf(-acc));
    }
}

// ---------------------------------------------------------------------------
// fuse via mma.sync bf16: out = LN(tokens + al*(h@W_rel^T) + (1-al)*(habs@W_abs^T))
// 256 CTAs x 256 threads; 64 rows each; warp covers 128 cols in 2 chunks of 64.
// ---------------------------------------------------------------------------
__global__ __launch_bounds__(LTPB, 1)
void fuse_mma_kernel(const float* __restrict__ tokens, const float* __restrict__ habs,
                     const float* __restrict__ W_abs,
                     const float* __restrict__ gamma, const float* __restrict__ beta,
                     float* __restrict__ out)
{
    extern __shared__ char smem[];
    uint32_t* hs   = (uint32_t*)(smem + FO_HS);    // [64][260] bf16x2
    float*    hb   = (float*)   (smem + FO_HB);    // [64][2]
    float*    redS = (float*)   (smem + FO_RS);    // [64][32]
    float*    redQ = (float*)   (smem + FO_RQ);    // [64][32]
    float*    mu_s = (float*)   (smem + FO_MU);    // [64]
    float*    rs_s = (float*)   (smem + FO_RV);    // [64]

    const int tid = threadIdx.x;
    const int lane = tid & 31, warpid = tid >> 5;
    const int q = lane & 3, g8 = lane >> 2;
    const int m0 = blockIdx.x * LM;

    // stage h (fp32 -> bf16x2) and habs
    for (int i = tid; i < LM*256; i += LTPB) {
        int row = i >> 8, kw = i & 255;
        float2 v = ((const float2*)(g_hn + (size_t)(m0 + row)*HIDN))[kw];
        __nv_bfloat162 p = __floats2bfloat162_rn(v.x, v.y);
        uint32_t u; memcpy(&u, &p, 4);
        hs[row*HSW + kw] = u;
    }
    for (int i = tid; i < LM*2; i += LTPB) hb[i] = habs[(size_t)m0*2 + i];
    __syncthreads();

    const float al = g_alpha[m0 >> 9], ali = 1.0f - al;
    const uint2* __restrict__ Wr64 = (const uint2*)g_Wrf;

    float rsum[8], rq[8];
    #pragma unroll
    for (int s = 0; s < 8; ++s) { rsum[s] = 0.0f; rq[s] = 0.0f; }

    #pragma unroll
    for (int ch = 0; ch < 2; ++ch) {
        float acc[4][8][4];
        #pragma unroll
        for (int mt = 0; mt < 4; ++mt)
            #pragma unroll
            for (int nt = 0; nt < 8; ++nt)
                #pragma unroll
                for (int c = 0; c < 4; ++c) acc[mt][nt][c] = 0.0f;

        const uint2* Bp = Wr64 + ((size_t)(warpid*2 + ch)*32*8)*32 + lane;
        uint2 bc[8], bn[8];
        #pragma unroll
        for (int nt = 0; nt < 8; ++nt) bc[nt] = Bp[nt*32];

        for (int ksl = 0; ksl < 32; ++ksl) {
            if (ksl < 31) {
                const uint2* Bn = Bp + (size_t)(ksl + 1) * 256;
                #pragma unroll
                for (int nt = 0; nt < 8; ++nt) bn[nt] = Bn[nt*32];
            }
            uint32_t a[4][4];
            const int kw = ksl * 8 + q;
            #pragma unroll
            for (int mt = 0; mt < 4; ++mt) {
                int r0 = (mt*16 + g8) * HSW + kw;
                a[mt][0] = hs[r0];
                a[mt][1] = hs[r0 + 8*HSW];
                a[mt][2] = hs[r0 + 4];
                a[mt][3] = hs[r0 + 8*HSW + 4];
            }
            #pragma unroll
            for (int nt = 0; nt < 8; ++nt) {
                #pragma unroll
                for (int mt = 0; mt < 4; ++mt)
                    MMA_BF16(acc[mt][nt], a[mt], bc[nt].x, bc[nt].y);
            }
            #pragma unroll
            for (int nt = 0; nt < 8; ++nt) bc[nt] = bn[nt];
        }

        // epilogue: blend + residual, write pre-LN x, accumulate row stats
        #pragma unroll
        for (int mt = 0; mt < 4; ++mt) {
            #pragma unroll
            for (int half = 0; half < 2; ++half) {
                const int row = mt*16 + g8 + half*8;
                const int R   = m0 + row;
                const float h0 = hb[row*2], h1 = hb[row*2+1];
                const int slot = mt*2 + half;
                #pragma unroll
                for (int nt = 0; nt < 8; ++nt) {
                    const int col = warpid*128 + ch*64 + nt*8 + q*2;
                    float2 tk  = *(const float2*)(tokens + (size_t)R*DIM + col);
                    float2 wa0 = ((const float2*)W_abs)[col];
                    float2 wa1 = ((const float2*)W_abs)[col+1];
                    float x0 = tk.x + al*acc[mt][nt][half*2  ] + ali*(h0*wa0.x + h1*wa0.y);
                    float x1 = tk.y + al*acc[mt][nt][half*2+1] + ali*(h0*wa1.x + h1*wa1.y);
                    *(float2*)(out + (size_t)R*DIM + col) = make_float2(x0, x1);
                    rsum[slot] += x0 + x1;
                    rq[slot]   += x0*x0 + x1*x1;
                }
            }
        }
    }

    // row-stat reduction
    __syncthreads();
    #pragma unroll
    for (int mt = 0; mt < 4; ++mt)
        #pragma unroll
        for (int half = 0; half < 2; ++half) {
            const int row = mt*16 + g8 + half*8;
            redS[row*32 + warpid*4 + q] = rsum[mt*2 + half];
            redQ[row*32 + warpid*4 + q] = rq[mt*2 + half];
        }
    __syncthreads();
    if (tid < LM) {
        float s = 0.0f, qq = 0.0f;
        #pragma unroll
        for (int i = 0; i < 32; ++i) { s += redS[tid*32 + i]; qq += redQ[tid*32 + i]; }
        float mu = s * (1.0f/DIM);
        float var = qq * (1.0f/DIM) - mu*mu;
        mu_s[tid] = mu; rs_s[tid] = rsqrtf(var + 1e-5f);
    }
    __syncthreads();

    // normalize
    for (int i = tid; i < (LM*DIM)/4; i += LTPB) {
        int mm = i >> 8, j4 = i & 255;
        float4 v = ((float4*)(out + (size_t)(m0 + mm)*DIM))[j4];
        float4 g = ((const float4*)gamma)[j4];
        float4 b = ((const float4*)beta)[j4];
        float mu = mu_s[mm], rr = rs_s[mm];
        v.x = (v.x - mu)*rr*g.x + b.x;
        v.y = (v.y - mu)*rr*g.y + b.y;
        v.z = (v.z - mu)*rr*g.z + b.z;
        v.w = (v.w - mu)*rr*g.w + b.w;
        ((float4*)(out + (size_t)(m0 + mm)*DIM))[j4] = v;
    }
}

// ---------------------------------------------------------------------------
extern "C" void kernel_launch(void* const* d_in, const int* in_sizes, int n_in,
                              void* d_out, int out_size)
{
    const float* tokens = (const float*)d_in[0];
    const float* traj   = (const float*)d_in[1];
    const float* habs   = (const float*)d_in[2];
    const float* espeed = (const float*)d_in[3];
    const float* gconf  = (const float*)d_in[4];
    const float* W_ih   = (const float*)d_in[5];
    const float* W_hh   = (const float*)d_in[6];
    const float* b_ih   = (const float*)d_in[7];
    const float* b_hh   = (const float*)d_in[8];
    const float* W_rel  = (const float*)d_in[9];
    const float* W_abs  = (const float*)d_in[10];
    const float* W_g1   = (const float*)d_in[11];
    const float* b_g1   = (const float*)d_in[12];
    const float* W_g2   = (const float*)d_in[13];
    const float* b_g2   = (const float*)d_in[14];
    const float* gamma  = (const float*)d_in[15];
    const float* beta   = (const float*)d_in[16];
    float* out = (float*)d_out;

    cudaFuncSetAttribute(lstm_mma_kernel, cudaFuncAttributeMaxDynamicSharedMemorySize, LSMEM);
    cudaFuncSetAttribute(fuse_mma_kernel, cudaFuncAttributeMaxDynamicSharedMemorySize, FSMEM);

    reorder_kernel<<<G4 + DIM, 128>>>(W_hh, W_ih, b_ih, b_hh, W_rel);
    lstm_mma_kernel<<<NCTA, LTPB, LSMEM>>>(traj);
    alpha_kernel<<<1, 32>>>(espeed, gconf, W_g1, b_g1, W_g2, b_g2);
    fuse_mma_kernel<<<NCTA, LTPB, FSMEM>>>(tokens, habs, W_abs, gamma, beta, out);
}